// round 2
// baseline (speedup 1.0000x reference)
#include <cuda_runtime.h>
#include <cuda_bf16.h>
#include <math.h>

// Problem constants
#define B_  2
#define T_  2048
#define E_  2048
#define HQ_ 32
#define HKV_ 8
#define HD_ 64
#define KVD_ (HKV_ * HD_)   // 512
#define M_  (B_ * T_)       // 4096

// Scratch (device globals — no allocation allowed)
__device__ float g_Q[(size_t)M_ * E_];    // [B*T, HQ*HD]
__device__ float g_K[(size_t)M_ * KVD_];  // [B*T, HKV*HD]
__device__ float g_V[(size_t)M_ * KVD_];  // [B*T, HKV*HD]
__device__ float g_A[(size_t)M_ * E_];    // attention output [B*T, HQ*HD]

// ---------------------------------------------------------------------------
// Tiled SGEMM: C[M,N] = A[M,K] @ B[K,N] (+bias). 64x64 tile, BK=16,
// 256 threads, 4x4 per-thread register blocking, float4 SMEM reads.
// All dims divisible by tiles (M=4096, N in {512,2048}, K=2048).
// ---------------------------------------------------------------------------
__global__ __launch_bounds__(256) void sgemm_kernel(
    const float* __restrict__ A, const float* __restrict__ Bm,
    float* __restrict__ C, int M, int N, int K,
    const float* __restrict__ bias)
{
    __shared__ float As[16][64];  // k-major
    __shared__ float Bs[16][64];

    const int tid = threadIdx.x;
    const int tx = tid & 15;
    const int ty = tid >> 4;
    const int row0 = blockIdx.y * 64;
    const int col0 = blockIdx.x * 64;

    float acc[4][4] = {};

    const int ar = tid >> 2;        // 0..63
    const int ac = (tid & 3) * 4;   // 0,4,8,12
    const int br = tid >> 4;        // 0..15
    const int bc = (tid & 15) * 4;  // 0..60

    const float* Aptr = A + (size_t)(row0 + ar) * K + ac;
    const float* Bptr = Bm + (size_t)br * N + col0 + bc;

    for (int k0 = 0; k0 < K; k0 += 16) {
        float4 av = *reinterpret_cast<const float4*>(Aptr + k0);
        float4 bv = *reinterpret_cast<const float4*>(Bptr + (size_t)k0 * N);
        As[ac + 0][ar] = av.x;
        As[ac + 1][ar] = av.y;
        As[ac + 2][ar] = av.z;
        As[ac + 3][ar] = av.w;
        *reinterpret_cast<float4*>(&Bs[br][bc]) = bv;
        __syncthreads();

#pragma unroll
        for (int k = 0; k < 16; k++) {
            float4 a4 = *reinterpret_cast<const float4*>(&As[k][ty * 4]);
            float4 b4 = *reinterpret_cast<const float4*>(&Bs[k][tx * 4]);
            float a[4] = {a4.x, a4.y, a4.z, a4.w};
            float b[4] = {b4.x, b4.y, b4.z, b4.w};
#pragma unroll
            for (int i = 0; i < 4; i++)
#pragma unroll
                for (int j = 0; j < 4; j++)
                    acc[i][j] = fmaf(a[i], b[j], acc[i][j]);
        }
        __syncthreads();
    }

    float4 bb = make_float4(0.f, 0.f, 0.f, 0.f);
    if (bias) bb = *reinterpret_cast<const float4*>(&bias[col0 + tx * 4]);

#pragma unroll
    for (int i = 0; i < 4; i++) {
        int r = row0 + ty * 4 + i;
        float4 o;
        o.x = acc[i][0] + bb.x;
        o.y = acc[i][1] + bb.y;
        o.z = acc[i][2] + bb.z;
        o.w = acc[i][3] + bb.w;
        *reinterpret_cast<float4*>(&C[(size_t)r * N + col0 + tx * 4]) = o;
    }
}

// ---------------------------------------------------------------------------
// Flash attention: one block = 64 queries x one query head x one batch.
// Online softmax over 32 key tiles of 64. 256 threads, 4x4 register blocking.
// SMEM rows padded to 65 floats -> <=2-way bank conflicts on all patterns.
// ---------------------------------------------------------------------------
__global__ __launch_bounds__(256) void attn_kernel(
    const float* __restrict__ Q, const float* __restrict__ K,
    const float* __restrict__ V, float* __restrict__ O)
{
    __shared__ float Qs[64][65];
    __shared__ float Ks[64][65];  // reused as P after S is computed
    __shared__ float Vs[64][65];

    const int tid = threadIdx.x;
    const int tx = tid & 15;
    const int ty = tid >> 4;
    const int q0 = blockIdx.x * 64;
    const int hq = blockIdx.y;
    const int b  = blockIdx.z;
    const int hkv = hq >> 2;  // GROUP = 4
    const float scale = 0.125f;  // 1/sqrt(64)

    // Load Q tile (scaled). 64 rows x 64 cols, 4 float4 per thread, coalesced.
#pragma unroll
    for (int i = 0; i < 4; i++) {
        int lin = tid + i * 256;
        int r = lin >> 4;
        int c = (lin & 15) * 4;
        float4 v = *reinterpret_cast<const float4*>(
            &Q[(size_t)(b * T_ + q0 + r) * E_ + hq * HD_ + c]);
        Qs[r][c + 0] = v.x * scale;
        Qs[r][c + 1] = v.y * scale;
        Qs[r][c + 2] = v.z * scale;
        Qs[r][c + 3] = v.w * scale;
    }

    float m[4], l[4], o[4][4];
#pragma unroll
    for (int i = 0; i < 4; i++) {
        m[i] = -INFINITY;
        l[i] = 0.f;
#pragma unroll
        for (int c = 0; c < 4; c++) o[i][c] = 0.f;
    }

    for (int kt = 0; kt < T_; kt += 64) {
        // Load K and V tiles (64x64 each), coalesced.
#pragma unroll
        for (int i = 0; i < 4; i++) {
            int lin = tid + i * 256;
            int r = lin >> 4;
            int c = (lin & 15) * 4;
            size_t base = (size_t)(b * T_ + kt + r) * KVD_ + hkv * HD_ + c;
            float4 kv = *reinterpret_cast<const float4*>(&K[base]);
            float4 vv = *reinterpret_cast<const float4*>(&V[base]);
            Ks[r][c + 0] = kv.x; Ks[r][c + 1] = kv.y;
            Ks[r][c + 2] = kv.z; Ks[r][c + 3] = kv.w;
            Vs[r][c + 0] = vv.x; Vs[r][c + 1] = vv.y;
            Vs[r][c + 2] = vv.z; Vs[r][c + 3] = vv.w;
        }
        __syncthreads();

        // S = Qs @ Ks^T (scaled already). 4x4 per thread.
        float p[4][4] = {};
#pragma unroll 8
        for (int d = 0; d < 64; d++) {
            float a[4], bb[4];
#pragma unroll
            for (int i = 0; i < 4; i++) a[i] = Qs[ty * 4 + i][d];
#pragma unroll
            for (int j = 0; j < 4; j++) bb[j] = Ks[tx * 4 + j][d];
#pragma unroll
            for (int i = 0; i < 4; i++)
#pragma unroll
                for (int j = 0; j < 4; j++)
                    p[i][j] = fmaf(a[i], bb[j], p[i][j]);
        }

        // Online softmax per row (row split across 16 tx lanes).
#pragma unroll
        for (int i = 0; i < 4; i++) {
            float rm = fmaxf(fmaxf(p[i][0], p[i][1]), fmaxf(p[i][2], p[i][3]));
#pragma unroll
            for (int off = 1; off < 16; off <<= 1)
                rm = fmaxf(rm, __shfl_xor_sync(0xffffffffu, rm, off));
            float mn = fmaxf(m[i], rm);
            float corr = __expf(m[i] - mn);
            float rs = 0.f;
#pragma unroll
            for (int j = 0; j < 4; j++) {
                p[i][j] = __expf(p[i][j] - mn);
                rs += p[i][j];
            }
#pragma unroll
            for (int off = 1; off < 16; off <<= 1)
                rs += __shfl_xor_sync(0xffffffffu, rs, off);
            l[i] = l[i] * corr + rs;
            m[i] = mn;
#pragma unroll
            for (int c = 0; c < 4; c++) o[i][c] *= corr;
        }

        __syncthreads();  // everyone done reading Ks before overwrite with P

        // Store P into Ks (as Ps[q][j])
#pragma unroll
        for (int i = 0; i < 4; i++)
#pragma unroll
            for (int j = 0; j < 4; j++)
                Ks[ty * 4 + i][tx * 4 + j] = p[i][j];
        __syncthreads();

        // O += P @ V
#pragma unroll 8
        for (int j = 0; j < 64; j++) {
            float pv[4], vv[4];
#pragma unroll
            for (int i = 0; i < 4; i++) pv[i] = Ks[ty * 4 + i][j];
#pragma unroll
            for (int c = 0; c < 4; c++) vv[c] = Vs[j][tx * 4 + c];
#pragma unroll
            for (int i = 0; i < 4; i++)
#pragma unroll
                for (int c = 0; c < 4; c++)
                    o[i][c] = fmaf(pv[i], vv[c], o[i][c]);
        }
        __syncthreads();  // before next tile overwrites Ks/Vs
    }

    // Epilogue: normalize and write [B*T, HQ*HD]
#pragma unroll
    for (int i = 0; i < 4; i++) {
        float inv = 1.f / l[i];
        int r = b * T_ + q0 + ty * 4 + i;
        float4 ov;
        ov.x = o[i][0] * inv;
        ov.y = o[i][1] * inv;
        ov.z = o[i][2] * inv;
        ov.w = o[i][3] * inv;
        *reinterpret_cast<float4*>(&g_A[(size_t)r * E_ + hq * HD_ + tx * 4]) = ov;
    }
}

// ---------------------------------------------------------------------------
extern "C" void kernel_launch(void* const* d_in, const int* in_sizes, int n_in,
                              void* d_out, int out_size)
{
    const float* x  = (const float*)d_in[0];
    const float* Wq = (const float*)d_in[1];
    const float* Wk = (const float*)d_in[2];
    const float* Wv = (const float*)d_in[3];
    const float* Wo = (const float*)d_in[4];
    const float* bo = (const float*)d_in[5];
    float* out = (float*)d_out;

    float *pQ, *pK, *pV, *pA;
    cudaGetSymbolAddress((void**)&pQ, g_Q);
    cudaGetSymbolAddress((void**)&pK, g_K);
    cudaGetSymbolAddress((void**)&pV, g_V);
    cudaGetSymbolAddress((void**)&pA, g_A);

    dim3 blk(256);

    // Q = x @ Wq   [4096 x 2048]
    sgemm_kernel<<<dim3(E_ / 64, M_ / 64), blk>>>(x, Wq, pQ, M_, E_, E_, nullptr);
    // K = x @ Wk   [4096 x 512]
    sgemm_kernel<<<dim3(KVD_ / 64, M_ / 64), blk>>>(x, Wk, pK, M_, KVD_, E_, nullptr);
    // V = x @ Wv   [4096 x 512]
    sgemm_kernel<<<dim3(KVD_ / 64, M_ / 64), blk>>>(x, Wv, pV, M_, KVD_, E_, nullptr);

    // Attention
    attn_kernel<<<dim3(T_ / 64, HQ_, B_), blk>>>(pQ, pK, pV, pA);

    // out = attn @ Wo + bo   [4096 x 2048]
    sgemm_kernel<<<dim3(E_ / 64, M_ / 64), blk>>>(pA, Wo, out, M_, E_, E_, bo);
}